// round 16
// baseline (speedup 1.0000x reference)
#include <cuda_runtime.h>
#include <cuda_fp16.h>
#include <cstdint>

// ============================================================================
// ClassicalSelfAttention B=4, N=4096, D=1024 fp32 — sm_103a via HMMA mma.sync.
//
//   U    = Wk^T Wq    (fp32 FFMA) -> fp16     [fused with Xh truncate]
//   Y    = X U^T      (fp16 HMMA) -> fp16
//   E_b  = exp(Y_b X_b^T /32 - 4) -> fp16, + per-CTA row partial sums (fused)
//   rinv = 1/rowsum  (4MB partial reduce)
//   O_b  = (E_b X_b) * rinv       (B from row-major Xh via ldmatrix.trans)
//
// R16: (1) A-fragment double-buffering inside each k-chunk — a[ks+1] LDSMs
// issue between the B loads and the 32 MMAs of ks, hiding the per-ks
// LDSM->MMA dependency head (+16 regs, ~253 total, still 2 CTAs/SM).
// (2) trunc + wgemm fused into one launch (block-range split) to overlap the
// memory-bound truncate with the compute-bound U GEMM.
// ============================================================================

#define SZ_XD ((size_t)4 * 4096 * 1024)
#define SZ_S  ((size_t)4 * 4096 * 4096)
__device__ __align__(16) __half g_Xh [SZ_XD];
__device__ __align__(16) __half g_Yh [SZ_XD];
__device__ __align__(16) __half g_Uh [1024*1024];
__device__ __align__(16) __half g_Ph [SZ_S];
__device__ __align__(16) float  g_Psum[16384 * 64];
__device__ __align__(16) float  g_Rinv[16384];

// ---------------- helpers ---------------------------------------------------
__device__ __forceinline__ uint32_t smem_u32(const void* p) {
    uint32_t a;
    asm("{ .reg .u64 t; cvta.to.shared.u64 t, %1; cvt.u32.u64 %0, t; }"
        : "=r"(a) : "l"(p));
    return a;
}
__device__ __forceinline__ void cp16(uint32_t s, const void* g) {
    asm volatile("cp.async.cg.shared.global [%0], [%1], 16;" :: "r"(s), "l"(g));
}
#define CP_COMMIT() asm volatile("cp.async.commit_group;" ::: "memory")
#define CP_WAIT1()  asm volatile("cp.async.wait_group 1;"  ::: "memory")

__device__ __forceinline__ uint32_t sw128(uint32_t off) {
    return off ^ ((off >> 3) & 0x70);
}
__device__ __forceinline__ void ldm4(uint32_t* r, uint32_t addr) {
    asm volatile("ldmatrix.sync.aligned.m8n8.x4.shared.b16 {%0,%1,%2,%3}, [%4];"
                 : "=r"(r[0]), "=r"(r[1]), "=r"(r[2]), "=r"(r[3]) : "r"(addr));
}
__device__ __forceinline__ void ldm4t(uint32_t* r, uint32_t addr) {
    asm volatile("ldmatrix.sync.aligned.m8n8.x4.trans.shared.b16 {%0,%1,%2,%3}, [%4];"
                 : "=r"(r[0]), "=r"(r[1]), "=r"(r[2]), "=r"(r[3]) : "r"(addr));
}
__device__ __forceinline__ void mma16816(float* c, const uint32_t* a,
                                         uint32_t b0, uint32_t b1) {
    asm volatile(
        "mma.sync.aligned.m16n8k16.row.col.f32.f16.f16.f32 "
        "{%0,%1,%2,%3}, {%4,%5,%6,%7}, {%8,%9}, {%0,%1,%2,%3};"
        : "+f"(c[0]), "+f"(c[1]), "+f"(c[2]), "+f"(c[3])
        : "r"(a[0]), "r"(a[1]), "r"(a[2]), "r"(a[3]), "r"(b0), "r"(b1));
}
__device__ __forceinline__ uint32_t pack2h(__half a, __half b) {
    return (uint32_t)__half_as_ushort(a) | ((uint32_t)__half_as_ushort(b) << 16);
}

// ============================================================================
// HMMA GEMM:  C[128,128] per CTA.  A[M,K] K-major fp16.
// BT=0: B[N,K] K-major (C = A B^T).   BT=1: B row-major [K,N] slab, ld ldB
// (C = A B), via ldmatrix.trans.
// MODE 0: Ch = fp16(acc)
// MODE 2: Ch = fp16(exp(acc/32-4)) + per-CTA row sums -> Psum[row][bx*2+nwarp]
// MODE 3: Cf = acc * Rinv[z*4096+row]
// 128 threads, 4 warps 2x2, 64x64 warptile; 3 stages x 32KB -> 2 CTAs/SM.
// Mainloop unrolled by 3 (stages % 3 == 1); A-fragments double-buffered
// across ks so MMAs of ks hide the A-LDSM latency of ks+1.
// ============================================================================
#define KCH 64
#define STAGE_BYTES 32768
#define NSTAGE 3

template<int MODE, int BT>
__global__ void __launch_bounds__(128, 2) gemm_k(
    const __half* __restrict__ Ah, const __half* __restrict__ Bh,
    float* __restrict__ Cf, __half* __restrict__ Ch,
    const float* __restrict__ Rinv, float* __restrict__ Psum,
    int Kdim, int ldB, int ldC, size_t sA, size_t sB, size_t sC)
{
    extern __shared__ __align__(1024) char smem[];
    const int tid  = threadIdx.x;
    const int wid  = tid >> 5;
    const int lane = tid & 31;
    const size_t z = blockIdx.z;

    const int m0 = blockIdx.y * 128;
    const int n0 = blockIdx.x * 128;
    const int mW = (wid >> 1) * 64;
    const int nW = (wid & 1) * 64;
    const uint32_t sb0 = smem_u32(smem);

    float acc[4][8][4];
#pragma unroll
    for (int i = 0; i < 4; i++)
#pragma unroll
        for (int j = 0; j < 8; j++)
#pragma unroll
            for (int r = 0; r < 4; r++) acc[i][j][r] = 0.f;

    // ---- A loader (K-major rows of 128B, SW128) ----------------------------
    const int rowL = tid >> 3, cA = tid & 7;
    const uint32_t soA = sw128((uint32_t)(rowL * 128 + cA * 16));
    const __half* pA = Ah + z * sA + (size_t)(m0 + rowL) * Kdim + cA * 8;
    const size_t strA = (size_t)16 * Kdim;

    // ---- B loader ----------------------------------------------------------
    const __half* pB;
    uint32_t soB;
    size_t strB, chB;
    if (BT == 0) {
        soB  = 16384 + soA;
        pB   = Bh + z * sB + (size_t)(n0 + rowL) * Kdim + cA * 8;
        strB = strA;
        chB  = KCH;
    } else {
        const int kr = tid >> 4, cB = tid & 15;
        soB  = 16384 + (uint32_t)(kr * 256 + ((cB ^ (kr & 7)) * 16));
        pB   = Bh + z * sB + (size_t)kr * ldB + n0 + cB * 8;
        strB = (size_t)8 * ldB;
        chB  = (size_t)KCH * ldB;
    }

    auto do_load = [&](uint32_t sb) {
#pragma unroll
        for (int i = 0; i < 8; i++)
            cp16(sb + soA + i * 2048, pA + i * strA);
#pragma unroll
        for (int i = 0; i < 8; i++)
            cp16(sb + soB + i * 2048, pB + i * strB);
        pA += KCH;  pB += chB;
    };

    const int stages = Kdim / KCH;   // == 1 (mod 3) at all call sites
    do_load(sb0);                       CP_COMMIT();
    do_load(sb0 + STAGE_BYTES);         CP_COMMIT();

    // ---- ldmatrix addressing ----------------------------------------------
    const int rl = lane & 15;
    const int kh = lane >> 4;
    uint32_t baseA[4], maskA[4];
#pragma unroll
    for (int mt = 0; mt < 4; mt++) {
        uint32_t row = (uint32_t)(mW + mt * 16 + rl);
        baseA[mt] = row * 128;
        maskA[mt] = (row << 4) & 0x70;
    }
    uint32_t baseB[4], maskB[4];
    uint32_t baseBT[4];
    if (BT == 0) {
#pragma unroll
        for (int np = 0; np < 4; np++) {
            uint32_t row = (uint32_t)(nW + np * 16 + rl);
            baseB[np] = 16384 + row * 128;
            maskB[np] = (row << 4) & 0x70;
        }
    } else {
        const int nWc = (wid & 1) * 8;
#pragma unroll
        for (int q = 0; q < 4; q++) {
            uint32_t krow  = (uint32_t)rl;
            uint32_t chunk = (uint32_t)(nWc + 2 * q + kh);
            baseBT[q] = 16384 + krow * 256 + ((chunk ^ (krow & 7)) * 16);
        }
    }

    // one k-chunk: A fragments double-buffered across the 4 k-steps.
    auto chunk = [&](uint32_t sb) {
        uint32_t a[2][4][4], b[4][4];
        // preload A for ks=0
        {
            const uint32_t c0 = kh * 16;
#pragma unroll
            for (int mt = 0; mt < 4; mt++)
                ldm4(a[0][mt], sb + baseA[mt] + (c0 ^ maskA[mt]));
        }
#pragma unroll
        for (int ks = 0; ks < 4; ks++) {
            const int cur = ks & 1, nxt = cur ^ 1;
            const uint32_t coloff = ks * 32 + kh * 16;
            // B fragments for this ks
            if (BT == 0) {
#pragma unroll
                for (int np = 0; np < 4; np++)
                    ldm4(b[np], sb + baseB[np] + (coloff ^ maskB[np]));
            } else {
#pragma unroll
                for (int q = 0; q < 4; q++)
                    ldm4t(b[q], sb + baseBT[q] + ks * 4096);
            }
            // prefetch A for ks+1 (its latency hidden under the MMAs below)
            if (ks < 3) {
                const uint32_t col2 = (ks + 1) * 32 + kh * 16;
#pragma unroll
                for (int mt = 0; mt < 4; mt++)
                    ldm4(a[nxt][mt], sb + baseA[mt] + (col2 ^ maskA[mt]));
            }
            // 32 independent MMAs on a[cur]
            if (BT == 0) {
#pragma unroll
                for (int mt = 0; mt < 4; mt++)
#pragma unroll
                    for (int nt = 0; nt < 8; nt++) {
                        const int np = nt >> 1, od = nt & 1;
                        mma16816(acc[mt][nt], a[cur][mt], b[np][od], b[np][od + 2]);
                    }
            } else {
#pragma unroll
                for (int mt = 0; mt < 4; mt++)
#pragma unroll
                    for (int nt = 0; nt < 8; nt++) {
                        const int q = nt >> 1, od = nt & 1;
                        mma16816(acc[mt][nt], a[cur][mt], b[q][od * 2], b[q][od * 2 + 1]);
                    }
            }
        }
    };

    // ---- mainloop: unrolled by 3; chunk THEN prefetch (R13 order) ----------
    int s = 0;
    for (; s + 3 <= stages; s += 3) {
#pragma unroll
        for (int u = 0; u < 3; u++) {
            CP_WAIT1();
            __syncthreads();
            chunk(sb0 + u * STAGE_BYTES);
            if (s + u + 2 < stages)
                do_load(sb0 + ((u + 2) % 3) * STAGE_BYTES);
            CP_COMMIT();
        }
    }
    for (; s < stages; s++) {       // tail: stages % 3 == 1 -> one iteration
        CP_WAIT1();
        __syncthreads();
        chunk(sb0 + (s % 3) * STAGE_BYTES);
    }

    // ---- epilogue ----------------------------------------------------------
    const int er = lane >> 2, ec = (lane & 3) * 2;
#pragma unroll
    for (int mt = 0; mt < 4; mt++) {
        const int row = m0 + mW + mt * 16 + er;
        float s0 = 0.f, s1 = 0.f;
#pragma unroll
        for (int nt = 0; nt < 8; nt++) {
            const int col = n0 + nW + nt * 8 + ec;
            if (MODE == 3) {
                const float r0 = Rinv[z * 4096 + row];
                const float r1 = Rinv[z * 4096 + row + 8];
                float* p0 = Cf + z * sC + (size_t)row * ldC + col;
                float* p1 = p0 + (size_t)8 * ldC;
                *(float2*)p0 = make_float2(acc[mt][nt][0] * r0, acc[mt][nt][1] * r0);
                *(float2*)p1 = make_float2(acc[mt][nt][2] * r1, acc[mt][nt][3] * r1);
            } else {
                float v0 = acc[mt][nt][0], v1 = acc[mt][nt][1];
                float v2 = acc[mt][nt][2], v3 = acc[mt][nt][3];
                if (MODE == 2) {
                    v0 = __expf(v0 * 0.03125f - 4.f);
                    v1 = __expf(v1 * 0.03125f - 4.f);
                    v2 = __expf(v2 * 0.03125f - 4.f);
                    v3 = __expf(v3 * 0.03125f - 4.f);
                    s0 += v0 + v1;
                    s1 += v2 + v3;
                }
                __half* base = Ch + z * sC;
                size_t o0 = (size_t)row * ldC + col;
                size_t o1 = o0 + (size_t)8 * ldC;
                *(uint32_t*)(base + o0) = pack2h(__float2half_rn(v0),
                                                 __float2half_rn(v1));
                *(uint32_t*)(base + o1) = pack2h(__float2half_rn(v2),
                                                 __float2half_rn(v3));
            }
        }
        if (MODE == 2) {
            s0 += __shfl_xor_sync(0xFFFFFFFF, s0, 1);
            s0 += __shfl_xor_sync(0xFFFFFFFF, s0, 2);
            s1 += __shfl_xor_sync(0xFFFFFFFF, s1, 1);
            s1 += __shfl_xor_sync(0xFFFFFFFF, s1, 2);
            if ((lane & 3) == 0) {
                const int slot = blockIdx.x * 2 + (wid & 1);
                Psum[((size_t)z * 4096 + row) * 64 + slot]     = s0;
                Psum[((size_t)z * 4096 + row + 8) * 64 + slot] = s1;
            }
        }
    }
}

// ============================================================================
// Fused prep: blocks [0,256) compute U = Wk^T Wq (64x64 tile each);
// blocks [256, 256+4096) truncate X -> Xh (4096 blocks x 4096 float4).
// Overlaps the memory-bound truncate with the compute-bound U GEMM.
// ============================================================================
__global__ void __launch_bounds__(256) prep_kernel(
    const float* __restrict__ Wk, const float* __restrict__ Wq,
    __half* __restrict__ Uh,
    const float* __restrict__ X, __half* __restrict__ Xh)
{
    if (blockIdx.x >= 256) {
        // ---- truncate slice: 1024 float4 per block -------------------------
        const int b = blockIdx.x - 256;                 // 0..4095
        const int i0 = b * 1024 + threadIdx.x;          // float4 index
#pragma unroll
        for (int r = 0; r < 4; r++) {
            int i = i0 + r * 256;
            float4 v = ((const float4*)X)[i];
            ((uint2*)Xh)[i] = make_uint2(
                pack2h(__float2half_rn(v.x), __float2half_rn(v.y)),
                pack2h(__float2half_rn(v.z), __float2half_rn(v.w)));
        }
        return;
    }

    // ---- wgemm 64x64 tile ---------------------------------------------------
    __shared__ float Ks[16][64];
    __shared__ float Qs[16][64];
    const int tid = threadIdx.x;
    const int e0 = (blockIdx.x >> 4) * 64, d0 = (blockIdx.x & 15) * 64;
    const int tx = tid & 15, ty = tid >> 4;

    float acc[4][4];
#pragma unroll
    for (int i = 0; i < 4; i++)
#pragma unroll
        for (int j = 0; j < 4; j++) acc[i][j] = 0.f;

    for (int k0 = 0; k0 < 1024; k0 += 16) {
        __syncthreads();
        {
            int j = tid >> 4, cc = (tid & 15) * 4;
            *(float4*)&Ks[j][cc] = *(const float4*)&Wk[(size_t)(k0 + j) * 1024 + e0 + cc];
            *(float4*)&Qs[j][cc] = *(const float4*)&Wq[(size_t)(k0 + j) * 1024 + d0 + cc];
        }
        __syncthreads();
#pragma unroll
        for (int kk = 0; kk < 16; kk++) {
            float ra[4], rb[4];
            *(float4*)&ra[0] = *(const float4*)&Ks[kk][ty * 4];
            *(float4*)&rb[0] = *(const float4*)&Qs[kk][tx * 4];
#pragma unroll
            for (int i = 0; i < 4; i++)
#pragma unroll
                for (int j = 0; j < 4; j++) acc[i][j] += ra[i] * rb[j];
        }
    }

#pragma unroll
    for (int i = 0; i < 4; i++) {
        const size_t e = e0 + ty * 4 + i;
#pragma unroll
        for (int j = 0; j < 4; j += 2) {
            size_t o = e * 1024 + d0 + tx * 4 + j;
            *(uint32_t*)(Uh + o) = pack2h(__float2half_rn(acc[i][j]),
                                          __float2half_rn(acc[i][j + 1]));
        }
    }
}

// ============================================================================
// rinv: reduce 64 partials per row, Rinv = 1/sum.
// ============================================================================
__global__ void __launch_bounds__(32) rinv_kernel(
    const float* __restrict__ Psum, float* __restrict__ Rinv)
{
    const size_t base = (size_t)blockIdx.x * 64;
    const int tid = threadIdx.x;
    float s = Psum[base + tid] + Psum[base + 32 + tid];
#pragma unroll
    for (int k = 16; k > 0; k >>= 1)
        s += __shfl_xor_sync(0xFFFFFFFF, s, k);
    if (tid == 0) Rinv[blockIdx.x] = 1.f / s;
}

// ============================================================================
// launch
// ============================================================================
extern "C" void kernel_launch(void* const* d_in, const int* in_sizes, int n_in,
                              void* d_out, int out_size)
{
    const float* x  = (const float*)d_in[0];
    const float* Wq = (const float*)d_in[1];
    const float* Wk = (const float*)d_in[2];
    float* out = (float*)d_out;

    __half *Xh, *Yh, *Uh, *Ph;
    float *Psum, *Rinv;
    cudaGetSymbolAddress((void**)&Xh,   g_Xh);
    cudaGetSymbolAddress((void**)&Yh,   g_Yh);
    cudaGetSymbolAddress((void**)&Uh,   g_Uh);
    cudaGetSymbolAddress((void**)&Ph,   g_Ph);
    cudaGetSymbolAddress((void**)&Psum, g_Psum);
    cudaGetSymbolAddress((void**)&Rinv, g_Rinv);

    cudaFuncSetAttribute(gemm_k<0,0>, cudaFuncAttributeMaxDynamicSharedMemorySize,
                         NSTAGE * STAGE_BYTES);
    cudaFuncSetAttribute(gemm_k<2,0>, cudaFuncAttributeMaxDynamicSharedMemorySize,
                         NSTAGE * STAGE_BYTES);
    cudaFuncSetAttribute(gemm_k<3,1>, cudaFuncAttributeMaxDynamicSharedMemorySize,
                         NSTAGE * STAGE_BYTES);

    const size_t sQK = (size_t)4096 * 1024;
    const size_t sS  = (size_t)4096 * 4096;
    const int smem = NSTAGE * STAGE_BYTES;

    // 1. fused prep: U GEMM (256 CTAs) + Xh truncate (4096 CTAs)
    prep_kernel<<<256 + 4096, 256>>>(Wk, Wq, Uh, x, Xh);

    // 2. Y = X U^T  (M=16384, N=1024, K=1024) -> fp16
    gemm_k<0,0><<<dim3(8, 128, 1), 128, smem>>>(
        Xh, Uh, nullptr, Yh, nullptr, nullptr, 1024, 0, 1024, 0, 0, 0);

    // 3. E_b = exp(Y_b X_b^T /32 - 4) -> Ph, + row partials -> Psum
    gemm_k<2,0><<<dim3(32, 32, 4), 128, smem>>>(
        Yh, Xh, nullptr, Ph, nullptr, Psum, 1024, 0, 4096, sQK, sQK, sS);

    // 4. Rinv = 1/rowsum
    rinv_kernel<<<16384, 32>>>(Psum, Rinv);

    // 5. O_b = (E_b X_b) * rinv -> fp32 out
    gemm_k<3,1><<<dim3(8, 32, 4), 128, smem>>>(
        Ph, Xh, out, nullptr, Rinv, nullptr, 4096, 1024, 1024, sS, sQK, sQK);
}

// round 17
// speedup vs baseline: 1.0091x; 1.0091x over previous
#include <cuda_runtime.h>
#include <cuda_fp16.h>
#include <cstdint>

// ============================================================================
// ClassicalSelfAttention B=4, N=4096, D=1024 fp32 — sm_103a via HMMA mma.sync.
//
//   U    = Wk^T Wq    (fp32 FFMA) -> fp16     [fused with Xh truncate]
//   Y    = X U^T      (fp16 HMMA) -> fp16
//   E_b  = exp(Y_b X_b^T /32 - 4) -> fp16, + per-CTA row partial sums (fused)
//   rinv = 1/rowsum  (4MB partial reduce, warp-per-row)
//   O_b  = (E_b X_b) * rinv       (B from row-major Xh via ldmatrix.trans)
//
// R17: revert R16's A-double-buffer (neutral, +16 regs of cliff risk); rinv
// rewritten warp-per-row with 256-thread blocks (was 1-warp blocks at 7.5%
// issue, 12us for a 4MB reduce -> predict ~3us).  GEMM mainloop = R15 exact
// (fastest measured; 55-60% tensor is this ISA's practical wall — six
// scheduling interventions all pinned there).
// ============================================================================

#define SZ_XD ((size_t)4 * 4096 * 1024)
#define SZ_S  ((size_t)4 * 4096 * 4096)
__device__ __align__(16) __half g_Xh [SZ_XD];
__device__ __align__(16) __half g_Yh [SZ_XD];
__device__ __align__(16) __half g_Uh [1024*1024];
__device__ __align__(16) __half g_Ph [SZ_S];
__device__ __align__(16) float  g_Psum[16384 * 64];
__device__ __align__(16) float  g_Rinv[16384];

// ---------------- helpers ---------------------------------------------------
__device__ __forceinline__ uint32_t smem_u32(const void* p) {
    uint32_t a;
    asm("{ .reg .u64 t; cvta.to.shared.u64 t, %1; cvt.u32.u64 %0, t; }"
        : "=r"(a) : "l"(p));
    return a;
}
__device__ __forceinline__ void cp16(uint32_t s, const void* g) {
    asm volatile("cp.async.cg.shared.global [%0], [%1], 16;" :: "r"(s), "l"(g));
}
#define CP_COMMIT() asm volatile("cp.async.commit_group;" ::: "memory")
#define CP_WAIT1()  asm volatile("cp.async.wait_group 1;"  ::: "memory")

__device__ __forceinline__ uint32_t sw128(uint32_t off) {
    return off ^ ((off >> 3) & 0x70);
}
__device__ __forceinline__ void ldm4(uint32_t* r, uint32_t addr) {
    asm volatile("ldmatrix.sync.aligned.m8n8.x4.shared.b16 {%0,%1,%2,%3}, [%4];"
                 : "=r"(r[0]), "=r"(r[1]), "=r"(r[2]), "=r"(r[3]) : "r"(addr));
}
__device__ __forceinline__ void ldm4t(uint32_t* r, uint32_t addr) {
    asm volatile("ldmatrix.sync.aligned.m8n8.x4.trans.shared.b16 {%0,%1,%2,%3}, [%4];"
                 : "=r"(r[0]), "=r"(r[1]), "=r"(r[2]), "=r"(r[3]) : "r"(addr));
}
__device__ __forceinline__ void mma16816(float* c, const uint32_t* a,
                                         uint32_t b0, uint32_t b1) {
    asm volatile(
        "mma.sync.aligned.m16n8k16.row.col.f32.f16.f16.f32 "
        "{%0,%1,%2,%3}, {%4,%5,%6,%7}, {%8,%9}, {%0,%1,%2,%3};"
        : "+f"(c[0]), "+f"(c[1]), "+f"(c[2]), "+f"(c[3])
        : "r"(a[0]), "r"(a[1]), "r"(a[2]), "r"(a[3]), "r"(b0), "r"(b1));
}
__device__ __forceinline__ uint32_t pack2h(__half a, __half b) {
    return (uint32_t)__half_as_ushort(a) | ((uint32_t)__half_as_ushort(b) << 16);
}

// ============================================================================
// HMMA GEMM:  C[128,128] per CTA.  A[M,K] K-major fp16.
// BT=0: B[N,K] K-major (C = A B^T).   BT=1: B row-major [K,N] slab, ld ldB
// (C = A B), via ldmatrix.trans.
// MODE 0: Ch = fp16(acc)
// MODE 2: Ch = fp16(exp(acc/32-4)) + per-CTA row sums -> Psum[row][bx*2+nwarp]
// MODE 3: Cf = acc * Rinv[z*4096+row]
// 128 threads, 4 warps 2x2, 64x64 warptile; 3 stages x 32KB -> 2 CTAs/SM.
// Mainloop unrolled by 3 (stages % 3 == 1); chunk-then-load order (R15 exact).
// ============================================================================
#define KCH 64
#define STAGE_BYTES 32768
#define NSTAGE 3

template<int MODE, int BT>
__global__ void __launch_bounds__(128, 2) gemm_k(
    const __half* __restrict__ Ah, const __half* __restrict__ Bh,
    float* __restrict__ Cf, __half* __restrict__ Ch,
    const float* __restrict__ Rinv, float* __restrict__ Psum,
    int Kdim, int ldB, int ldC, size_t sA, size_t sB, size_t sC)
{
    extern __shared__ __align__(1024) char smem[];
    const int tid  = threadIdx.x;
    const int wid  = tid >> 5;
    const int lane = tid & 31;
    const size_t z = blockIdx.z;

    const int m0 = blockIdx.y * 128;
    const int n0 = blockIdx.x * 128;
    const int mW = (wid >> 1) * 64;
    const int nW = (wid & 1) * 64;
    const uint32_t sb0 = smem_u32(smem);

    float acc[4][8][4];
#pragma unroll
    for (int i = 0; i < 4; i++)
#pragma unroll
        for (int j = 0; j < 8; j++)
#pragma unroll
            for (int r = 0; r < 4; r++) acc[i][j][r] = 0.f;

    // ---- A loader (K-major rows of 128B, SW128) ----------------------------
    const int rowL = tid >> 3, cA = tid & 7;
    const uint32_t soA = sw128((uint32_t)(rowL * 128 + cA * 16));
    const __half* pA = Ah + z * sA + (size_t)(m0 + rowL) * Kdim + cA * 8;
    const size_t strA = (size_t)16 * Kdim;

    // ---- B loader ----------------------------------------------------------
    const __half* pB;
    uint32_t soB;
    size_t strB, chB;
    if (BT == 0) {
        soB  = 16384 + soA;
        pB   = Bh + z * sB + (size_t)(n0 + rowL) * Kdim + cA * 8;
        strB = strA;
        chB  = KCH;
    } else {
        const int kr = tid >> 4, cB = tid & 15;
        soB  = 16384 + (uint32_t)(kr * 256 + ((cB ^ (kr & 7)) * 16));
        pB   = Bh + z * sB + (size_t)kr * ldB + n0 + cB * 8;
        strB = (size_t)8 * ldB;
        chB  = (size_t)KCH * ldB;
    }

    auto do_load = [&](uint32_t sb) {
#pragma unroll
        for (int i = 0; i < 8; i++)
            cp16(sb + soA + i * 2048, pA + i * strA);
#pragma unroll
        for (int i = 0; i < 8; i++)
            cp16(sb + soB + i * 2048, pB + i * strB);
        pA += KCH;  pB += chB;
    };

    const int stages = Kdim / KCH;   // == 1 (mod 3) at all call sites
    do_load(sb0);                       CP_COMMIT();
    do_load(sb0 + STAGE_BYTES);         CP_COMMIT();

    // ---- ldmatrix addressing ----------------------------------------------
    const int rl = lane & 15;
    const int kh = lane >> 4;
    uint32_t baseA[4], maskA[4];
#pragma unroll
    for (int mt = 0; mt < 4; mt++) {
        uint32_t row = (uint32_t)(mW + mt * 16 + rl);
        baseA[mt] = row * 128;
        maskA[mt] = (row << 4) & 0x70;
    }
    uint32_t baseB[4], maskB[4];
    uint32_t baseBT[4];
    if (BT == 0) {
#pragma unroll
        for (int np = 0; np < 4; np++) {
            uint32_t row = (uint32_t)(nW + np * 16 + rl);
            baseB[np] = 16384 + row * 128;
            maskB[np] = (row << 4) & 0x70;
        }
    } else {
        const int nWc = (wid & 1) * 8;
#pragma unroll
        for (int q = 0; q < 4; q++) {
            uint32_t krow  = (uint32_t)rl;
            uint32_t chunk = (uint32_t)(nWc + 2 * q + kh);
            baseBT[q] = 16384 + krow * 256 + ((chunk ^ (krow & 7)) * 16);
        }
    }

    auto chunk = [&](uint32_t sb) {
#pragma unroll
        for (int ks = 0; ks < 4; ks++) {
            uint32_t a[4][4], b[4][4];
            const uint32_t coloff = ks * 32 + kh * 16;
#pragma unroll
            for (int mt = 0; mt < 4; mt++)
                ldm4(a[mt], sb + baseA[mt] + (coloff ^ maskA[mt]));
            if (BT == 0) {
#pragma unroll
                for (int np = 0; np < 4; np++)
                    ldm4(b[np], sb + baseB[np] + (coloff ^ maskB[np]));
#pragma unroll
                for (int mt = 0; mt < 4; mt++)
#pragma unroll
                    for (int nt = 0; nt < 8; nt++) {
                        const int np = nt >> 1, od = nt & 1;
                        mma16816(acc[mt][nt], a[mt], b[np][od], b[np][od + 2]);
                    }
            } else {
#pragma unroll
                for (int q = 0; q < 4; q++)
                    ldm4t(b[q], sb + baseBT[q] + ks * 4096);
#pragma unroll
                for (int mt = 0; mt < 4; mt++)
#pragma unroll
                    for (int nt = 0; nt < 8; nt++) {
                        const int q = nt >> 1, od = nt & 1;
                        mma16816(acc[mt][nt], a[mt], b[q][od * 2], b[q][od * 2 + 1]);
                    }
            }
        }
    };

    // ---- mainloop: unrolled by 3; chunk THEN prefetch ----------------------
    int s = 0;
    for (; s + 3 <= stages; s += 3) {
#pragma unroll
        for (int u = 0; u < 3; u++) {
            CP_WAIT1();
            __syncthreads();
            chunk(sb0 + u * STAGE_BYTES);
            if (s + u + 2 < stages)
                do_load(sb0 + ((u + 2) % 3) * STAGE_BYTES);
            CP_COMMIT();
        }
    }
    for (; s < stages; s++) {       // tail: stages % 3 == 1 -> one iteration
        CP_WAIT1();
        __syncthreads();
        chunk(sb0 + (s % 3) * STAGE_BYTES);
    }

    // ---- epilogue ----------------------------------------------------------
    const int er = lane >> 2, ec = (lane & 3) * 2;
#pragma unroll
    for (int mt = 0; mt < 4; mt++) {
        const int row = m0 + mW + mt * 16 + er;
        float s0 = 0.f, s1 = 0.f;
#pragma unroll
        for (int nt = 0; nt < 8; nt++) {
            const int col = n0 + nW + nt * 8 + ec;
            if (MODE == 3) {
                const float r0 = Rinv[z * 4096 + row];
                const float r1 = Rinv[z * 4096 + row + 8];
                float* p0 = Cf + z * sC + (size_t)row * ldC + col;
                float* p1 = p0 + (size_t)8 * ldC;
                *(float2*)p0 = make_float2(acc[mt][nt][0] * r0, acc[mt][nt][1] * r0);
                *(float2*)p1 = make_float2(acc[mt][nt][2] * r1, acc[mt][nt][3] * r1);
            } else {
                float v0 = acc[mt][nt][0], v1 = acc[mt][nt][1];
                float v2 = acc[mt][nt][2], v3 = acc[mt][nt][3];
                if (MODE == 2) {
                    v0 = __expf(v0 * 0.03125f - 4.f);
                    v1 = __expf(v1 * 0.03125f - 4.f);
                    v2 = __expf(v2 * 0.03125f - 4.f);
                    v3 = __expf(v3 * 0.03125f - 4.f);
                    s0 += v0 + v1;
                    s1 += v2 + v3;
                }
                __half* base = Ch + z * sC;
                size_t o0 = (size_t)row * ldC + col;
                size_t o1 = o0 + (size_t)8 * ldC;
                *(uint32_t*)(base + o0) = pack2h(__float2half_rn(v0),
                                                 __float2half_rn(v1));
                *(uint32_t*)(base + o1) = pack2h(__float2half_rn(v2),
                                                 __float2half_rn(v3));
            }
        }
        if (MODE == 2) {
            s0 += __shfl_xor_sync(0xFFFFFFFF, s0, 1);
            s0 += __shfl_xor_sync(0xFFFFFFFF, s0, 2);
            s1 += __shfl_xor_sync(0xFFFFFFFF, s1, 1);
            s1 += __shfl_xor_sync(0xFFFFFFFF, s1, 2);
            if ((lane & 3) == 0) {
                const int slot = blockIdx.x * 2 + (wid & 1);
                Psum[((size_t)z * 4096 + row) * 64 + slot]     = s0;
                Psum[((size_t)z * 4096 + row + 8) * 64 + slot] = s1;
            }
        }
    }
}

// ============================================================================
// Fused prep: blocks [0,256) compute U = Wk^T Wq (64x64 tile each);
// blocks [256, 256+4096) truncate X -> Xh.
// ============================================================================
__global__ void __launch_bounds__(256) prep_kernel(
    const float* __restrict__ Wk, const float* __restrict__ Wq,
    __half* __restrict__ Uh,
    const float* __restrict__ X, __half* __restrict__ Xh)
{
    if (blockIdx.x >= 256) {
        const int b = blockIdx.x - 256;
        const int i0 = b * 1024 + threadIdx.x;
#pragma unroll
        for (int r = 0; r < 4; r++) {
            int i = i0 + r * 256;
            float4 v = ((const float4*)X)[i];
            ((uint2*)Xh)[i] = make_uint2(
                pack2h(__float2half_rn(v.x), __float2half_rn(v.y)),
                pack2h(__float2half_rn(v.z), __float2half_rn(v.w)));
        }
        return;
    }

    __shared__ float Ks[16][64];
    __shared__ float Qs[16][64];
    const int tid = threadIdx.x;
    const int e0 = (blockIdx.x >> 4) * 64, d0 = (blockIdx.x & 15) * 64;
    const int tx = tid & 15, ty = tid >> 4;

    float acc[4][4];
#pragma unroll
    for (int i = 0; i < 4; i++)
#pragma unroll
        for (int j = 0; j < 4; j++) acc[i][j] = 0.f;

    for (int k0 = 0; k0 < 1024; k0 += 16) {
        __syncthreads();
        {
            int j = tid >> 4, cc = (tid & 15) * 4;
            *(float4*)&Ks[j][cc] = *(const float4*)&Wk[(size_t)(k0 + j) * 1024 + e0 + cc];
            *(float4*)&Qs[j][cc] = *(const float4*)&Wq[(size_t)(k0 + j) * 1024 + d0 + cc];
        }
        __syncthreads();
#pragma unroll
        for (int kk = 0; kk < 16; kk++) {
            float ra[4], rb[4];
            *(float4*)&ra[0] = *(const float4*)&Ks[kk][ty * 4];
            *(float4*)&rb[0] = *(const float4*)&Qs[kk][tx * 4];
#pragma unroll
            for (int i = 0; i < 4; i++)
#pragma unroll
                for (int j = 0; j < 4; j++) acc[i][j] += ra[i] * rb[j];
        }
    }

#pragma unroll
    for (int i = 0; i < 4; i++) {
        const size_t e = e0 + ty * 4 + i;
#pragma unroll
        for (int j = 0; j < 4; j += 2) {
            size_t o = e * 1024 + d0 + tx * 4 + j;
            *(uint32_t*)(Uh + o) = pack2h(__float2half_rn(acc[i][j]),
                                          __float2half_rn(acc[i][j + 1]));
        }
    }
}

// ============================================================================
// rinv: warp-per-row (8 rows per 256-thread block), lane sums 2 partials,
// shfl tree -> Rinv = 1/sum.  grid 2048.
// ============================================================================
__global__ void __launch_bounds__(256) rinv_kernel(
    const float* __restrict__ Psum, float* __restrict__ Rinv)
{
    const int wid  = threadIdx.x >> 5;
    const int lane = threadIdx.x & 31;
    const int row  = blockIdx.x * 8 + wid;       // 2048 * 8 = 16384 rows
    const size_t base = (size_t)row * 64;
    float s = Psum[base + lane] + Psum[base + 32 + lane];
#pragma unroll
    for (int k = 16; k > 0; k >>= 1)
        s += __shfl_xor_sync(0xFFFFFFFF, s, k);
    if (lane == 0) Rinv[row] = 1.f / s;
}

// ============================================================================
// launch
// ============================================================================
extern "C" void kernel_launch(void* const* d_in, const int* in_sizes, int n_in,
                              void* d_out, int out_size)
{
    const float* x  = (const float*)d_in[0];
    const float* Wq = (const float*)d_in[1];
    const float* Wk = (const float*)d_in[2];
    float* out = (float*)d_out;

    __half *Xh, *Yh, *Uh, *Ph;
    float *Psum, *Rinv;
    cudaGetSymbolAddress((void**)&Xh,   g_Xh);
    cudaGetSymbolAddress((void**)&Yh,   g_Yh);
    cudaGetSymbolAddress((void**)&Uh,   g_Uh);
    cudaGetSymbolAddress((void**)&Ph,   g_Ph);
    cudaGetSymbolAddress((void**)&Psum, g_Psum);
    cudaGetSymbolAddress((void**)&Rinv, g_Rinv);

    cudaFuncSetAttribute(gemm_k<0,0>, cudaFuncAttributeMaxDynamicSharedMemorySize,
                         NSTAGE * STAGE_BYTES);
    cudaFuncSetAttribute(gemm_k<2,0>, cudaFuncAttributeMaxDynamicSharedMemorySize,
                         NSTAGE * STAGE_BYTES);
    cudaFuncSetAttribute(gemm_k<3,1>, cudaFuncAttributeMaxDynamicSharedMemorySize,
                         NSTAGE * STAGE_BYTES);

    const size_t sQK = (size_t)4096 * 1024;
    const size_t sS  = (size_t)4096 * 4096;
    const int smem = NSTAGE * STAGE_BYTES;

    // 1. fused prep: U GEMM (256 CTAs) + Xh truncate (4096 CTAs)
    prep_kernel<<<256 + 4096, 256>>>(Wk, Wq, Uh, x, Xh);

    // 2. Y = X U^T  (M=16384, N=1024, K=1024) -> fp16
    gemm_k<0,0><<<dim3(8, 128, 1), 128, smem>>>(
        Xh, Uh, nullptr, Yh, nullptr, nullptr, 1024, 0, 1024, 0, 0, 0);

    // 3. E_b = exp(Y_b X_b^T /32 - 4) -> Ph, + row partials -> Psum
    gemm_k<2,0><<<dim3(32, 32, 4), 128, smem>>>(
        Yh, Xh, nullptr, Ph, nullptr, Psum, 1024, 0, 4096, sQK, sQK, sS);

    // 4. Rinv = 1/rowsum  (warp-per-row)
    rinv_kernel<<<2048, 256>>>(Psum, Rinv);

    // 5. O_b = (E_b X_b) * rinv -> fp32 out
    gemm_k<3,1><<<dim3(8, 32, 4), 128, smem>>>(
        Ph, Xh, out, nullptr, Rinv, nullptr, 4096, 1024, 1024, sS, sQK, sQK);
}